// round 15
// baseline (speedup 1.0000x reference)
#include <cuda_runtime.h>
#include <cstdint>

#define NB   64
#define LSEQ 512
#define NE   64
#define NH   8
#define ND   8
#define LN_EPS 1e-5f

__device__ __forceinline__ void cp16(uint32_t dst, const void* src) {
    asm volatile("cp.async.ca.shared.global [%0], [%1], 16;" :: "r"(dst), "l"(src) : "memory");
}
__device__ __forceinline__ void cp_commit() {
    asm volatile("cp.async.commit_group;" ::: "memory");
}
__device__ __forceinline__ void cp_wait0() {
    asm volatile("cp.async.wait_group 0;" ::: "memory");
}
__device__ __forceinline__ float ex2(float x) {
    float r; asm("ex2.approx.f32 %0, %1;" : "=f"(r) : "f"(x)); return r;
}

// Scratch: projected Q/K/V in head-major layout [B, H, L, D]
static __device__ float g_qh[NB * NH * LSEQ * ND];
static __device__ float g_kh[NB * NH * LSEQ * ND];
static __device__ float g_vh[NB * NH * LSEQ * ND];

// ---------------------------------------------------------------------------
// Kernel 1: fused QKV projection (scale*log2e folded into Wq/bq) — unchanged.
// ---------------------------------------------------------------------------
struct __align__(16) Smem1 {
    float xq[64 * 68];
    float xk[64 * 68];
    float w[3][64 * 64];
    float bias[3][64];
};

__global__ __launch_bounds__(256, 1) void proj_kernel(
    const float* __restrict__ qin, const float* __restrict__ kin,
    const float* __restrict__ Wq, const float* __restrict__ bq,
    const float* __restrict__ Wk, const float* __restrict__ bk,
    const float* __restrict__ Wv, const float* __restrict__ bv)
{
    extern __shared__ char smem_raw[];
    Smem1& s = *reinterpret_cast<Smem1*>(smem_raw);
    const int t = threadIdx.x;
    const int row0 = blockIdx.x * 64;
    const float scale = 0.3535533905932738f * 1.4426950408889634f; // rsqrt(8)*log2e

    {
        const float4* q4 = reinterpret_cast<const float4*>(qin + (size_t)row0 * NE);
        const float4* k4 = reinterpret_cast<const float4*>(kin + (size_t)row0 * NE);
        #pragma unroll
        for (int ss = 0; ss < 4; ss++) {
            int f = t + 256 * ss;
            int r = f >> 4, e4 = f & 15;
            *reinterpret_cast<float4*>(&s.xq[r * 68 + e4 * 4]) = q4[f];
            *reinterpret_cast<float4*>(&s.xk[r * 68 + e4 * 4]) = k4[f];
        }
    }
    {
        const float* Ws[3] = {Wq, Wk, Wv};
        #pragma unroll
        for (int m = 0; m < 3; m++) {
            float sc = (m == 0) ? scale : 1.0f;
            const float4* w4 = reinterpret_cast<const float4*>(Ws[m]);
            #pragma unroll
            for (int ss = 0; ss < 4; ss++) {
                int f = t + 256 * ss;
                int c = f >> 4, e4 = f & 15;
                float4 v = w4[f];
                s.w[m][(e4 * 4 + 0) * 64 + c] = v.x * sc;
                s.w[m][(e4 * 4 + 1) * 64 + c] = v.y * sc;
                s.w[m][(e4 * 4 + 2) * 64 + c] = v.z * sc;
                s.w[m][(e4 * 4 + 3) * 64 + c] = v.w * sc;
            }
        }
        if (t < 64) {
            s.bias[0][t] = bq[t] * scale;
            s.bias[1][t] = bk[t];
            s.bias[2][t] = bv[t];
        }
    }
    __syncthreads();

    const int rg = t >> 4;
    const int cg = t & 15;
    float* outs[3] = {g_qh, g_kh, g_vh};

    #pragma unroll
    for (int m = 0; m < 3; m++) {
        const float* xin = (m == 0) ? s.xq : s.xk;
        float acc[4][4] = {};
        #pragma unroll 16
        for (int e = 0; e < 64; e++) {
            float4 w = *reinterpret_cast<const float4*>(&s.w[m][e * 64 + cg * 4]);
            #pragma unroll
            for (int rr = 0; rr < 4; rr++) {
                float x = xin[(rg * 4 + rr) * 68 + e];
                acc[rr][0] = fmaf(x, w.x, acc[rr][0]);
                acc[rr][1] = fmaf(x, w.y, acc[rr][1]);
                acc[rr][2] = fmaf(x, w.z, acc[rr][2]);
                acc[rr][3] = fmaf(x, w.w, acc[rr][3]);
            }
        }
        const int h = cg >> 1, d0 = (cg & 1) * 4;
        #pragma unroll
        for (int rr = 0; rr < 4; rr++) {
            int row = row0 + rg * 4 + rr;
            int bb = row >> 9, pos = row & 511;
            float4 o;
            o.x = acc[rr][0] + s.bias[m][cg * 4 + 0];
            o.y = acc[rr][1] + s.bias[m][cg * 4 + 1];
            o.z = acc[rr][2] + s.bias[m][cg * 4 + 2];
            o.w = acc[rr][3] + s.bias[m][cg * 4 + 3];
            *reinterpret_cast<float4*>(
                &outs[m][(((size_t)bb * NH + h) * LSEQ + pos) * ND + d0]) = o;
        }
    }
}

// ---------------------------------------------------------------------------
// Kernel 2: attention, row-per-lane layout @ 1024 threads (occ 50%).
// Warp w owns keys [w*16, w*16+16); lane j owns query row j of the 32-row
// tile. K/V smem reads are warp-broadcasts; softmax-sum and ctx reduce via
// a small smem partial matrix (no shuffles). 64 regs/thread.
// Smem float offsets (manual layout, 186,240 bytes total):
// ---------------------------------------------------------------------------
#define QPITCH   12
#define OFF_K    0          // k[2][4096]
#define OFF_V    8192       // v[2][4096]
#define OFF_Q    16384      // q[2][32*QPITCH]
#define OFF_CTXP 17152      // [32 warps][32 rows * 12] (slots 0-7 ctx, 8 psum)
#define OFF_SINV 29440      // [32]
#define OFF_CTXF 29472      // [32][68]
#define OFF_W    31648      // [3][4096]
#define OFF_VEC  43936      // bo,b1,b2,g1,be1,g2,be2 : 7*64
#define OFF_XROW 44384      // [32][68]
#define SMEM2_FLOATS 46560
// attT (attn transpose buffer) overlays OFF_K..: [32][516] = 16512 <= 17152

__global__ __launch_bounds__(1024, 1) void attn_kernel(
    const float* __restrict__ prev,
    const float* __restrict__ Wo, const float* __restrict__ bo,
    const float* __restrict__ ln1g, const float* __restrict__ ln1b,
    const float* __restrict__ W1, const float* __restrict__ b1,
    const float* __restrict__ W2, const float* __restrict__ b2,
    const float* __restrict__ ln2g, const float* __restrict__ ln2b,
    float* __restrict__ out, float* __restrict__ attn)
{
    extern __shared__ float smf[];
    const int t  = threadIdx.x;
    const int bb = blockIdx.y;
    const int l0 = blockIdx.x * 32;
    const int wid = t >> 5;
    const int j   = t & 31;

    const float4* kh_base = reinterpret_cast<const float4*>(
        g_kh + ((size_t)bb * NH) * LSEQ * ND);
    const float4* vh_base = reinterpret_cast<const float4*>(
        g_vh + ((size_t)bb * NH) * LSEQ * ND);
    const float4* qh_base = reinterpret_cast<const float4*>(
        g_qh + ((size_t)bb * NH) * LSEQ * ND);
    const int HSTRIDE = LSEQ * ND / 4;   // 1024 float4 per head
    const int QOFF    = l0 * 2;          // float4 offset of tile's q rows

    auto stage = [&](int hh) {
        const int nb = hh & 1;
        cp16((uint32_t)__cvta_generic_to_shared(smf + OFF_K + nb * 4096 + t * 4),
             kh_base + (size_t)hh * HSTRIDE + t);
        cp16((uint32_t)__cvta_generic_to_shared(smf + OFF_V + nb * 4096 + t * 4),
             vh_base + (size_t)hh * HSTRIDE + t);
        if (t < 64) {
            int jr = t >> 1, half = t & 1;
            cp16((uint32_t)__cvta_generic_to_shared(
                     smf + OFF_Q + nb * (32 * QPITCH) + jr * QPITCH + half * 4),
                 qh_base + (size_t)hh * HSTRIDE + QOFF + t);
        }
        cp_commit();
    };

    stage(0);

    // Epilogue weights (transposed) + vectors (overlaps with cp.async)
    {
        const float* Ws[3] = {Wo, W1, W2};
        #pragma unroll
        for (int m = 0; m < 3; m++) {
            const float4* w4 = reinterpret_cast<const float4*>(Ws[m]);
            int c = t >> 4, e4 = t & 15;
            float4 v = w4[t];
            smf[OFF_W + m * 4096 + (e4 * 4 + 0) * 64 + c] = v.x;
            smf[OFF_W + m * 4096 + (e4 * 4 + 1) * 64 + c] = v.y;
            smf[OFF_W + m * 4096 + (e4 * 4 + 2) * 64 + c] = v.z;
            smf[OFF_W + m * 4096 + (e4 * 4 + 3) * 64 + c] = v.w;
        }
        if (t < 64) {
            smf[OFF_VEC + 0 * 64 + t] = bo[t];
            smf[OFF_VEC + 1 * 64 + t] = b1[t];
            smf[OFF_VEC + 2 * 64 + t] = b2[t];
            smf[OFF_VEC + 3 * 64 + t] = ln1g[t];
            smf[OFF_VEC + 4 * 64 + t] = ln1b[t];
            smf[OFF_VEC + 5 * 64 + t] = ln2g[t];
            smf[OFF_VEC + 6 * 64 + t] = ln2b[t];
        }
    }

    cp_wait0();
    __syncthreads();           // head-0 staging + weights visible

    float aacc[16];
    #pragma unroll
    for (int m = 0; m < 16; m++) aacc[m] = 0.f;

    #pragma unroll 1
    for (int h = 0; h < NH; h++) {
        if (h + 1 < NH) stage(h + 1);     // overlaps this head's compute
        const int nb = h & 1;
        const float* kw = smf + OFF_K + nb * 4096 + wid * 128;  // 16 keys * 8
        const float* vw = smf + OFF_V + nb * 4096 + wid * 128;
        const float* qb = smf + OFF_Q + nb * (32 * QPITCH) + j * QPITCH;

        float qr[8];
        *reinterpret_cast<float4*>(&qr[0]) = *reinterpret_cast<const float4*>(&qb[0]);
        *reinterpret_cast<float4*>(&qr[4]) = *reinterpret_cast<const float4*>(&qb[4]);

        // scores for row j against this warp's 16 keys (broadcast K loads)
        float p[16];
        #pragma unroll
        for (int m = 0; m < 16; m++) {
            float4 k0 = *reinterpret_cast<const float4*>(&kw[m * 8]);
            float4 k1 = *reinterpret_cast<const float4*>(&kw[m * 8 + 4]);
            p[m] = qr[0]*k0.x + qr[1]*k0.y + qr[2]*k0.z + qr[3]*k0.w
                 + qr[4]*k1.x + qr[5]*k1.y + qr[6]*k1.z + qr[7]*k1.w;
        }
        float psum = 0.f;
        #pragma unroll
        for (int m = 0; m < 16; m++) { p[m] = ex2(p[m]); psum += p[m]; }

        // ctx partials for row j over this warp's keys (broadcast V loads)
        float cpx[8];
        #pragma unroll
        for (int d = 0; d < 8; d++) cpx[d] = 0.f;
        #pragma unroll
        for (int m = 0; m < 16; m++) {
            float4 v0 = *reinterpret_cast<const float4*>(&vw[m * 8]);
            float4 v1 = *reinterpret_cast<const float4*>(&vw[m * 8 + 4]);
            float pm = p[m];
            cpx[0] = fmaf(pm, v0.x, cpx[0]); cpx[1] = fmaf(pm, v0.y, cpx[1]);
            cpx[2] = fmaf(pm, v0.z, cpx[2]); cpx[3] = fmaf(pm, v0.w, cpx[3]);
            cpx[4] = fmaf(pm, v1.x, cpx[4]); cpx[5] = fmaf(pm, v1.y, cpx[5]);
            cpx[6] = fmaf(pm, v1.z, cpx[6]); cpx[7] = fmaf(pm, v1.w, cpx[7]);
        }

        // store partials: ctxp[wid][j][0..7]=ctx, [8]=psum
        {
            float* cb = smf + OFF_CTXP + wid * 384 + j * 12;
            *reinterpret_cast<float4*>(&cb[0]) = make_float4(cpx[0], cpx[1], cpx[2], cpx[3]);
            *reinterpret_cast<float4*>(&cb[4]) = make_float4(cpx[4], cpx[5], cpx[6], cpx[7]);
            cb[8] = psum;
        }
        __syncthreads();   // SYNC_B: partials visible

        // reducers: t<256 sum ctx over 32 warps; warp 8 computes 1/rowsum
        float raw = 0.f;
        const int rr = t >> 3, dd2 = t & 7;
        if (t < 256) {
            #pragma unroll
            for (int w2 = 0; w2 < 32; w2++)
                raw += smf[OFF_CTXP + w2 * 384 + rr * 12 + dd2];
        } else if (t < 288) {
            int r2 = t & 31;
            float ssum = 0.f;
            #pragma unroll
            for (int w2 = 0; w2 < 32; w2++)
                ssum += smf[OFF_CTXP + w2 * 384 + r2 * 12 + 8];
            smf[OFF_SINV + r2] = 1.0f / ssum;
        }
        cp_wait0();        // own copies for head h+1 done
        __syncthreads();   // SYNC_C: sinv + next-head staging visible

        // attention-mean accumulation + normalized ctx write
        const float si = smf[OFF_SINV + j];
        #pragma unroll
        for (int m = 0; m < 16; m++) aacc[m] = fmaf(p[m], si, aacc[m]);
        if (t < 256) {
            float sir = smf[OFF_SINV + rr];
            smf[OFF_CTXF + rr * 68 + h * 8 + dd2] = raw * sir;
        }
    }

    // ---- attn output: transpose via dead K/V smem, then coalesced stores ----
    {
        float* attT = smf;       // overlays k/v/q region: [32][516]
        #pragma unroll
        for (int m = 0; m < 16; m++)
            attT[j * 516 + wid * 16 + m] = aacc[m] * 0.125f;
        __syncthreads();         // attT + ctxf(h=7) visible
        float* attb = attn + ((size_t)bb * LSEQ + l0) * LSEQ;
        #pragma unroll
        for (int ss = 0; ss < 4; ss++) {
            int f4 = t + 1024 * ss;
            int row = f4 >> 7, c4 = f4 & 127;
            float4 vv = *reinterpret_cast<const float4*>(&attT[row * 516 + c4 * 4]);
            *reinterpret_cast<float4*>(&attb[(size_t)row * LSEQ + c4 * 4]) = vv;
        }
    }

    // ---- fused epilogue on threads < 512: Wo+res+LN1+FF+res+LN2 ----
    if (t < 512) {
        const int r  = t >> 4;
        const int cg = t & 15;
        const size_t grow = (size_t)bb * LSEQ + l0 + r;
        const float* ctx  = smf + OFF_CTXF;
        const float* wsm  = smf + OFF_W;
        const float* vbo  = smf + OFF_VEC;
        float* xrow = smf + OFF_XROW;

        float x0, x1, x2, x3;
        {
            float a0 = vbo[cg*4+0], a1 = vbo[cg*4+1], a2 = vbo[cg*4+2], a3 = vbo[cg*4+3];
            #pragma unroll 16
            for (int e = 0; e < 64; e++) {
                float xx = ctx[r * 68 + e];
                float4 w = *reinterpret_cast<const float4*>(&wsm[e * 64 + cg * 4]);
                a0 = fmaf(xx, w.x, a0); a1 = fmaf(xx, w.y, a1);
                a2 = fmaf(xx, w.z, a2); a3 = fmaf(xx, w.w, a3);
            }
            const float4 pv = *reinterpret_cast<const float4*>(&prev[grow * NE + cg * 4]);
            a0 += pv.x; a1 += pv.y; a2 += pv.z; a3 += pv.w;

            float psum = a0 + a1 + a2 + a3;
            #pragma unroll
            for (int o = 8; o >= 1; o >>= 1) psum += __shfl_xor_sync(0xffffffffu, psum, o);
            float mu = psum * (1.0f / 64.0f);
            float d0 = a0 - mu, d1 = a1 - mu, d2 = a2 - mu, d3 = a3 - mu;
            float psq = d0*d0 + d1*d1 + d2*d2 + d3*d3;
            #pragma unroll
            for (int o = 8; o >= 1; o >>= 1) psq += __shfl_xor_sync(0xffffffffu, psq, o);
            float rs = rsqrtf(psq * (1.0f / 64.0f) + LN_EPS);
            x0 = fmaf(d0 * rs, vbo[192+cg*4+0], vbo[256+cg*4+0]);
            x1 = fmaf(d1 * rs, vbo[192+cg*4+1], vbo[256+cg*4+1]);
            x2 = fmaf(d2 * rs, vbo[192+cg*4+2], vbo[256+cg*4+2]);
            x3 = fmaf(d3 * rs, vbo[192+cg*4+3], vbo[256+cg*4+3]);
            xrow[r*68 + cg*4+0] = x0; xrow[r*68 + cg*4+1] = x1;
            xrow[r*68 + cg*4+2] = x2; xrow[r*68 + cg*4+3] = x3;
        }
        __syncwarp();

        float h0, h1, h2, h3;
        {   // FF layer 1 + ReLU (into registers, then in-place into xrow)
            float a0 = vbo[64+cg*4+0], a1 = vbo[64+cg*4+1], a2 = vbo[64+cg*4+2], a3 = vbo[64+cg*4+3];
            #pragma unroll 16
            for (int e = 0; e < 64; e++) {
                float xx = xrow[r * 68 + e];
                float4 w = *reinterpret_cast<const float4*>(&wsm[4096 + e * 64 + cg * 4]);
                a0 = fmaf(xx, w.x, a0); a1 = fmaf(xx, w.y, a1);
                a2 = fmaf(xx, w.z, a2); a3 = fmaf(xx, w.w, a3);
            }
            h0 = fmaxf(a0, 0.f); h1 = fmaxf(a1, 0.f);
            h2 = fmaxf(a2, 0.f); h3 = fmaxf(a3, 0.f);
        }
        __syncwarp();
        xrow[r*68 + cg*4+0] = h0; xrow[r*68 + cg*4+1] = h1;
        xrow[r*68 + cg*4+2] = h2; xrow[r*68 + cg*4+3] = h3;
        __syncwarp();

        {   // FF layer 2 + residual + LN2 + output write
            float a0 = vbo[128+cg*4+0], a1 = vbo[128+cg*4+1], a2 = vbo[128+cg*4+2], a3 = vbo[128+cg*4+3];
            #pragma unroll 16
            for (int e = 0; e < 64; e++) {
                float hh = xrow[r * 68 + e];
                float4 w = *reinterpret_cast<const float4*>(&wsm[8192 + e * 64 + cg * 4]);
                a0 = fmaf(hh, w.x, a0); a1 = fmaf(hh, w.y, a1);
                a2 = fmaf(hh, w.z, a2); a3 = fmaf(hh, w.w, a3);
            }
            a0 += x0; a1 += x1; a2 += x2; a3 += x3;

            float psum = a0 + a1 + a2 + a3;
            #pragma unroll
            for (int o = 8; o >= 1; o >>= 1) psum += __shfl_xor_sync(0xffffffffu, psum, o);
            float mu = psum * (1.0f / 64.0f);
            float d0 = a0 - mu, d1 = a1 - mu, d2 = a2 - mu, d3 = a3 - mu;
            float psq = d0*d0 + d1*d1 + d2*d2 + d3*d3;
            #pragma unroll
            for (int o = 8; o >= 1; o >>= 1) psq += __shfl_xor_sync(0xffffffffu, psq, o);
            float rs = rsqrtf(psq * (1.0f / 64.0f) + LN_EPS);

            float4 o4;
            o4.x = fmaf(d0 * rs, vbo[320+cg*4+0], vbo[384+cg*4+0]);
            o4.y = fmaf(d1 * rs, vbo[320+cg*4+1], vbo[384+cg*4+1]);
            o4.z = fmaf(d2 * rs, vbo[320+cg*4+2], vbo[384+cg*4+2]);
            o4.w = fmaf(d3 * rs, vbo[320+cg*4+3], vbo[384+cg*4+3]);
            *reinterpret_cast<float4*>(&out[grow * NE + cg * 4]) = o4;
        }
    }
}

// ---------------------------------------------------------------------------
extern "C" void kernel_launch(void* const* d_in, const int* in_sizes, int n_in,
                              void* d_out, int out_size)
{
    const float* q    = (const float*)d_in[0];
    const float* k    = (const float*)d_in[1];
    const float* prev = (const float*)d_in[2];
    const float* Wq   = (const float*)d_in[3];
    const float* bq   = (const float*)d_in[4];
    const float* Wk   = (const float*)d_in[5];
    const float* bk   = (const float*)d_in[6];
    const float* Wv   = (const float*)d_in[7];
    const float* bv   = (const float*)d_in[8];
    const float* Wo   = (const float*)d_in[9];
    const float* bo   = (const float*)d_in[10];
    const float* g1   = (const float*)d_in[11];
    const float* be1  = (const float*)d_in[12];
    const float* W1   = (const float*)d_in[13];
    const float* b1   = (const float*)d_in[14];
    const float* W2   = (const float*)d_in[15];
    const float* b2   = (const float*)d_in[16];
    const float* g2   = (const float*)d_in[17];
    const float* be2  = (const float*)d_in[18];

    float* out  = (float*)d_out;
    float* attn = out + (size_t)NB * LSEQ * NE;

    cudaFuncSetAttribute(proj_kernel, cudaFuncAttributeMaxDynamicSharedMemorySize,
                         (int)sizeof(Smem1));
    cudaFuncSetAttribute(attn_kernel, cudaFuncAttributeMaxDynamicSharedMemorySize,
                         SMEM2_FLOATS * 4);

    proj_kernel<<<(NB * LSEQ) / 64, 256, sizeof(Smem1)>>>(
        q, k, Wq, bq, Wk, bk, Wv, bv);
    attn_kernel<<<dim3(LSEQ / 32, NB), 1024, SMEM2_FLOATS * 4>>>(
        prev, Wo, bo, g1, be1, W1, b1, W2, b2, g2, be2, out, attn);
}

// round 16
// speedup vs baseline: 1.0982x; 1.0982x over previous
#include <cuda_runtime.h>
#include <cstdint>

#define NB   64
#define LSEQ 512
#define NE   64
#define NH   8
#define ND   8
#define LN_EPS 1e-5f

using ull = unsigned long long;

__device__ __forceinline__ void cp16(uint32_t dst, const void* src) {
    asm volatile("cp.async.ca.shared.global [%0], [%1], 16;" :: "r"(dst), "l"(src) : "memory");
}
__device__ __forceinline__ void cp_commit() {
    asm volatile("cp.async.commit_group;" ::: "memory");
}
__device__ __forceinline__ void cp_wait0() {
    asm volatile("cp.async.wait_group 0;" ::: "memory");
}
__device__ __forceinline__ void bar_pair(int id) {
    asm volatile("bar.sync %0, 64;" :: "r"(id) : "memory");
}
__device__ __forceinline__ float ex2(float x) {
    float r; asm("ex2.approx.f32 %0, %1;" : "=f"(r) : "f"(x)); return r;
}
__device__ __forceinline__ ull pk2(float a, float b) {
    ull r; asm("mov.b64 %0, {%1, %2};" : "=l"(r) : "f"(a), "f"(b)); return r;
}
__device__ __forceinline__ void upk2(ull v, float& a, float& b) {
    asm("mov.b64 {%0, %1}, %2;" : "=f"(a), "=f"(b) : "l"(v));
}
__device__ __forceinline__ ull fma2(ull a, ull b, ull c) {
    ull d; asm("fma.rn.f32x2 %0, %1, %2, %3;" : "=l"(d) : "l"(a), "l"(b), "l"(c)); return d;
}
__device__ __forceinline__ ull mul2(ull a, ull b) {
    ull d; asm("mul.rn.f32x2 %0, %1, %2;" : "=l"(d) : "l"(a), "l"(b)); return d;
}
__device__ __forceinline__ ull add2(ull a, ull b) {
    ull d; asm("add.rn.f32x2 %0, %1, %2;" : "=l"(d) : "l"(a), "l"(b)); return d;
}

// Scratch buffers
static __device__ float g_qh[NB * NH * LSEQ * ND];
static __device__ float g_kh[NB * NH * LSEQ * ND];
static __device__ float g_vh[NB * NH * LSEQ * ND];
static __device__ float g_ctx[NB * LSEQ * NE];   // attention context rows

// ---------------------------------------------------------------------------
// Kernel 1: fused QKV projection (scale*log2e folded into Wq/bq) — unchanged.
// ---------------------------------------------------------------------------
struct __align__(16) Smem1 {
    float xq[64 * 68];
    float xk[64 * 68];
    float w[3][64 * 64];
    float bias[3][64];
};

__global__ __launch_bounds__(256, 1) void proj_kernel(
    const float* __restrict__ qin, const float* __restrict__ kin,
    const float* __restrict__ Wq, const float* __restrict__ bq,
    const float* __restrict__ Wk, const float* __restrict__ bk,
    const float* __restrict__ Wv, const float* __restrict__ bv)
{
    extern __shared__ char smem_raw[];
    Smem1& s = *reinterpret_cast<Smem1*>(smem_raw);
    const int t = threadIdx.x;
    const int row0 = blockIdx.x * 64;
    const float scale = 0.3535533905932738f * 1.4426950408889634f; // rsqrt(8)*log2e

    {
        const float4* q4 = reinterpret_cast<const float4*>(qin + (size_t)row0 * NE);
        const float4* k4 = reinterpret_cast<const float4*>(kin + (size_t)row0 * NE);
        #pragma unroll
        for (int ss = 0; ss < 4; ss++) {
            int f = t + 256 * ss;
            int r = f >> 4, e4 = f & 15;
            *reinterpret_cast<float4*>(&s.xq[r * 68 + e4 * 4]) = q4[f];
            *reinterpret_cast<float4*>(&s.xk[r * 68 + e4 * 4]) = k4[f];
        }
    }
    {
        const float* Ws[3] = {Wq, Wk, Wv};
        #pragma unroll
        for (int m = 0; m < 3; m++) {
            float sc = (m == 0) ? scale : 1.0f;
            const float4* w4 = reinterpret_cast<const float4*>(Ws[m]);
            #pragma unroll
            for (int ss = 0; ss < 4; ss++) {
                int f = t + 256 * ss;
                int c = f >> 4, e4 = f & 15;
                float4 v = w4[f];
                s.w[m][(e4 * 4 + 0) * 64 + c] = v.x * sc;
                s.w[m][(e4 * 4 + 1) * 64 + c] = v.y * sc;
                s.w[m][(e4 * 4 + 2) * 64 + c] = v.z * sc;
                s.w[m][(e4 * 4 + 3) * 64 + c] = v.w * sc;
            }
        }
        if (t < 64) {
            s.bias[0][t] = bq[t] * scale;
            s.bias[1][t] = bk[t];
            s.bias[2][t] = bv[t];
        }
    }
    __syncthreads();

    const int rg = t >> 4;
    const int cg = t & 15;
    float* outs[3] = {g_qh, g_kh, g_vh};

    #pragma unroll
    for (int m = 0; m < 3; m++) {
        const float* xin = (m == 0) ? s.xq : s.xk;
        float acc[4][4] = {};
        #pragma unroll 16
        for (int e = 0; e < 64; e++) {
            float4 w = *reinterpret_cast<const float4*>(&s.w[m][e * 64 + cg * 4]);
            #pragma unroll
            for (int rr = 0; rr < 4; rr++) {
                float x = xin[(rg * 4 + rr) * 68 + e];
                acc[rr][0] = fmaf(x, w.x, acc[rr][0]);
                acc[rr][1] = fmaf(x, w.y, acc[rr][1]);
                acc[rr][2] = fmaf(x, w.z, acc[rr][2]);
                acc[rr][3] = fmaf(x, w.w, acc[rr][3]);
            }
        }
        const int h = cg >> 1, d0 = (cg & 1) * 4;
        #pragma unroll
        for (int rr = 0; rr < 4; rr++) {
            int row = row0 + rg * 4 + rr;
            int bb = row >> 9, pos = row & 511;
            float4 o;
            o.x = acc[rr][0] + s.bias[m][cg * 4 + 0];
            o.y = acc[rr][1] + s.bias[m][cg * 4 + 1];
            o.z = acc[rr][2] + s.bias[m][cg * 4 + 2];
            o.w = acc[rr][3] + s.bias[m][cg * 4 + 3];
            *reinterpret_cast<float4*>(
                &outs[m][(((size_t)bb * NH + h) * LSEQ + pos) * ND + d0]) = o;
        }
    }
}

// ---------------------------------------------------------------------------
// Kernel 2: attention. R13 shape (4 rows/warp, m-split 2, d-packed f32x2)
// at 256 threads / 16-row tiles / 128 regs -> 2 CTAs per SM so barrier and
// memory stalls of one CTA are hidden by the other. Epilogue split out.
// Smem float offsets:
// ---------------------------------------------------------------------------
#define KPITCH    12
#define A_OFF_K   0                    // k[2][512*12] = 12288
#define A_OFF_V   12288                // v[2][512*12] = 12288
#define A_OFF_Q   24576                // q[2][16*8]   = 256
#define A_OFF_PS  24832                // psum[2][16]  = 32
#define A_OFF_CXP 24864                // ctxp[2][16*64] = 2048
#define A_SMEM_FLOATS 26912            // 107,648 bytes

__global__ __launch_bounds__(256, 2) void attn_kernel(float* __restrict__ attn)
{
    extern __shared__ float smf[];
    const int t  = threadIdx.x;
    const int bb = blockIdx.y;
    const int l0 = blockIdx.x * 16;

    const float4* kh_base = reinterpret_cast<const float4*>(
        g_kh + ((size_t)bb * NH) * LSEQ * ND);
    const float4* vh_base = reinterpret_cast<const float4*>(
        g_vh + ((size_t)bb * NH) * LSEQ * ND);
    const float4* qh_base = reinterpret_cast<const float4*>(
        g_qh + ((size_t)bb * NH) * LSEQ * ND);
    const int HSTRIDE = LSEQ * ND / 4;   // 1024 float4 per head
    const int QOFF    = l0 * 2;          // float4 offset of this tile's q rows

    auto stage = [&](int hh) {
        const int nb = hh & 1;
        const float4* kg4 = kh_base + (size_t)hh * HSTRIDE;
        const float4* vg4 = vh_base + (size_t)hh * HSTRIDE;
        #pragma unroll
        for (int ss = 0; ss < 4; ss++) {
            int f = t + 256 * ss;             // 0..1023
            int m = f >> 1, half = f & 1;
            cp16((uint32_t)__cvta_generic_to_shared(
                     smf + A_OFF_K + nb * 6144 + m * KPITCH + half * 4), kg4 + f);
            cp16((uint32_t)__cvta_generic_to_shared(
                     smf + A_OFF_V + nb * 6144 + m * KPITCH + half * 4), vg4 + f);
        }
        if (t < 32) {
            cp16((uint32_t)__cvta_generic_to_shared(smf + A_OFF_Q + nb * 128 + t * 4),
                 qh_base + (size_t)hh * HSTRIDE + QOFF + t);
        }
        cp_commit();
    };

    stage(0);

    const int wid  = t >> 5;
    const int j    = t & 31;
    const int g    = wid & 1;          // key half
    const int r0   = (wid >> 1) * 4;   // rows r0..r0+3 (of 16)
    const int mb   = g * 256 + j;
    const int pair = (wid >> 1) + 1;   // named barrier ids 1..4

    const int sel  = (j >> 4) & 1;
    const int sel2 = (j >> 3) & 1;
    const int sel3 = (j >> 2) & 1;
    const int dd   = sel * 4 + sel2 * 2 + sel3;
    const int rowidx = sel * 2 + sel2;

    float aacc[4][8];
    #pragma unroll
    for (int r = 0; r < 4; r++)
        #pragma unroll
        for (int i = 0; i < 8; i++) aacc[r][i] = 0.f;

    #pragma unroll 1
    for (int h = 0; h < NH; h++) {
        cp_wait0();
        __syncthreads();
        if (h + 1 < NH) stage(h + 1);

        const int nb = h & 1;
        const float* kb = smf + A_OFF_K + nb * 6144;
        const float* vb = smf + A_OFF_V + nb * 6144;
        const float* qb = smf + A_OFF_Q + nb * 128;

        // q rows as packed d-pairs
        ull qp0[4], qp1[4], qp2[4], qp3[4];
        {
            const ulonglong2* qa = reinterpret_cast<const ulonglong2*>(&qb[(r0 + 0) * 8]);
            const ulonglong2* qc = reinterpret_cast<const ulonglong2*>(&qb[(r0 + 1) * 8]);
            const ulonglong2* qd = reinterpret_cast<const ulonglong2*>(&qb[(r0 + 2) * 8]);
            const ulonglong2* qe = reinterpret_cast<const ulonglong2*>(&qb[(r0 + 3) * 8]);
            qp0[0] = qa[0].x; qp0[1] = qa[0].y; qp0[2] = qa[1].x; qp0[3] = qa[1].y;
            qp1[0] = qc[0].x; qp1[1] = qc[0].y; qp1[2] = qc[1].x; qp1[3] = qc[1].y;
            qp2[0] = qd[0].x; qp2[1] = qd[0].y; qp2[2] = qd[1].x; qp2[3] = qd[1].y;
            qp3[0] = qe[0].x; qp3[1] = qe[0].y; qp3[2] = qe[1].x; qp3[3] = qe[1].y;
        }

        // ---- scores: d-packed f32x2 ----
        float s0[8], s1[8], s2[8], s3[8];
        #pragma unroll
        for (int i = 0; i < 8; i++) {
            int m = mb + i * 32;
            ulonglong2 kA = *reinterpret_cast<const ulonglong2*>(&kb[m * KPITCH]);
            ulonglong2 kB = *reinterpret_cast<const ulonglong2*>(&kb[m * KPITCH + 4]);
            ull a0 = mul2(qp0[3], kB.y);
            a0 = fma2(qp0[2], kB.x, a0);
            a0 = fma2(qp0[1], kA.y, a0);
            a0 = fma2(qp0[0], kA.x, a0);
            ull a1 = mul2(qp1[3], kB.y);
            a1 = fma2(qp1[2], kB.x, a1);
            a1 = fma2(qp1[1], kA.y, a1);
            a1 = fma2(qp1[0], kA.x, a1);
            ull a2 = mul2(qp2[3], kB.y);
            a2 = fma2(qp2[2], kB.x, a2);
            a2 = fma2(qp2[1], kA.y, a2);
            a2 = fma2(qp2[0], kA.x, a2);
            ull a3 = mul2(qp3[3], kB.y);
            a3 = fma2(qp3[2], kB.x, a3);
            a3 = fma2(qp3[1], kA.y, a3);
            a3 = fma2(qp3[0], kA.x, a3);
            float lo, hi;
            upk2(a0, lo, hi); s0[i] = lo + hi;
            upk2(a1, lo, hi); s1[i] = lo + hi;
            upk2(a2, lo, hi); s2[i] = lo + hi;
            upk2(a3, lo, hi); s3[i] = lo + hi;
        }

        // ---- exp2 + per-lane partial sums ----
        float sum0 = 0.f, sum1 = 0.f, sum2 = 0.f, sum3 = 0.f;
        #pragma unroll
        for (int i = 0; i < 8; i++) {
            s0[i] = ex2(s0[i]); sum0 += s0[i];
            s1[i] = ex2(s1[i]); sum1 += s1[i];
            s2[i] = ex2(s2[i]); sum2 += s2[i];
            s3[i] = ex2(s3[i]); sum3 += s3[i];
        }
        // ---- 6-shfl value-halving sum reduction ----
        {
            float k0 = sel ? sum2 : sum0, n0 = sel ? sum0 : sum2;
            float k1v = sel ? sum3 : sum1, n1 = sel ? sum1 : sum3;
            float t0 = k0  + __shfl_xor_sync(0xffffffffu, n0, 16);
            float t1 = k1v + __shfl_xor_sync(0xffffffffu, n1, 16);
            float kk = sel2 ? t1 : t0, nn = sel2 ? t0 : t1;
            float v  = kk + __shfl_xor_sync(0xffffffffu, nn, 8);
            v += __shfl_xor_sync(0xffffffffu, v, 4);
            v += __shfl_xor_sync(0xffffffffu, v, 2);
            v += __shfl_xor_sync(0xffffffffu, v, 1);
            if ((j & 7) == 0) smf[A_OFF_PS + g * 16 + r0 + rowidx] = v;
        }
        bar_pair(pair);

        const float4 pa = *reinterpret_cast<const float4*>(&smf[A_OFF_PS + r0]);
        const float4 pb = *reinterpret_cast<const float4*>(&smf[A_OFF_PS + 16 + r0]);
        const float i0 = 1.0f / (pa.x + pb.x);
        const float i1 = 1.0f / (pa.y + pb.y);
        const float i2 = 1.0f / (pa.z + pb.z);
        const float i3 = 1.0f / (pa.w + pb.w);

        // ---- attention-mean accumulation ----
        #pragma unroll
        for (int i = 0; i < 8; i++) {
            aacc[0][i] = fmaf(s0[i], i0, aacc[0][i]);
            aacc[1][i] = fmaf(s1[i], i1, aacc[1][i]);
            aacc[2][i] = fmaf(s2[i], i2, aacc[2][i]);
            aacc[3][i] = fmaf(s3[i], i3, aacc[3][i]);
        }

        // ---- ctx partials, d-packed ----
        ull cp0[4] = {}, cp1[4] = {}, cp2[4] = {}, cp3[4] = {};
        #pragma unroll
        for (int i = 0; i < 8; i++) {
            int m = mb + i * 32;
            ulonglong2 vA = *reinterpret_cast<const ulonglong2*>(&vb[m * KPITCH]);
            ulonglong2 vB = *reinterpret_cast<const ulonglong2*>(&vb[m * KPITCH + 4]);
            ull pp0 = pk2(s0[i], s0[i]);
            ull pp1 = pk2(s1[i], s1[i]);
            ull pp2 = pk2(s2[i], s2[i]);
            ull pp3 = pk2(s3[i], s3[i]);
            cp0[0] = fma2(pp0, vA.x, cp0[0]); cp0[1] = fma2(pp0, vA.y, cp0[1]);
            cp0[2] = fma2(pp0, vB.x, cp0[2]); cp0[3] = fma2(pp0, vB.y, cp0[3]);
            cp1[0] = fma2(pp1, vA.x, cp1[0]); cp1[1] = fma2(pp1, vA.y, cp1[1]);
            cp1[2] = fma2(pp1, vB.x, cp1[2]); cp1[3] = fma2(pp1, vB.y, cp1[3]);
            cp2[0] = fma2(pp2, vA.x, cp2[0]); cp2[1] = fma2(pp2, vA.y, cp2[1]);
            cp2[2] = fma2(pp2, vB.x, cp2[2]); cp2[3] = fma2(pp2, vB.y, cp2[3]);
            cp3[0] = fma2(pp3, vA.x, cp3[0]); cp3[1] = fma2(pp3, vA.y, cp3[1]);
            cp3[2] = fma2(pp3, vB.x, cp3[2]); cp3[3] = fma2(pp3, vB.y, cp3[3]);
        }

        // ---- packed value-halving butterfly per row ----
        float fin[4];
        ull* cps[4] = {cp0, cp1, cp2, cp3};
        const float invr[4] = {i0, i1, i2, i3};
        #pragma unroll
        for (int r = 0; r < 4; r++) {
            ull* cp = cps[r];
            ull t2[2];
            #pragma unroll
            for (int kk = 0; kk < 2; kk++) {
                ull snd  = sel ? cp[kk]     : cp[2 + kk];
                ull kept = sel ? cp[2 + kk] : cp[kk];
                t2[kk] = add2(kept, __shfl_xor_sync(0xffffffffu, snd, 16));
            }
            ull snd  = sel2 ? t2[0] : t2[1];
            ull kept = sel2 ? t2[1] : t2[0];
            ull u = add2(kept, __shfl_xor_sync(0xffffffffu, snd, 8));
            float lo, hi;
            upk2(u, lo, hi);
            float kept_s = sel3 ? hi : lo;
            float snd_s  = sel3 ? lo : hi;
            float f = kept_s + __shfl_xor_sync(0xffffffffu, snd_s, 4);
            f += __shfl_xor_sync(0xffffffffu, f, 2);
            f += __shfl_xor_sync(0xffffffffu, f, 1);
            fin[r] = f * invr[r];
        }
        if ((j & 3) == 0) {
            #pragma unroll
            for (int r = 0; r < 4; r++)
                smf[A_OFF_CXP + g * 1024 + (r0 + r) * 64 + h * 8 + dd] = fin[r];
        }
    }

    // ---- attn output (head mean), coalesced 128B per warp-row ----
    {
        float* base = attn + ((size_t)bb * LSEQ + l0) * LSEQ;
        #pragma unroll
        for (int r = 0; r < 4; r++) {
            float* rowp = base + (size_t)(r0 + r) * LSEQ + g * 256 + j;
            #pragma unroll
            for (int i = 0; i < 8; i++)
                rowp[i * 32] = aacc[r][i] * 0.125f;
        }
    }
    __syncthreads();

    // ---- combine key-half ctx partials, write ctx rows to gmem ----
    {
        const float4* c0 = reinterpret_cast<const float4*>(smf + A_OFF_CXP);
        const float4* c1 = reinterpret_cast<const float4*>(smf + A_OFF_CXP + 1024);
        float4* dst = reinterpret_cast<float4*>(
            g_ctx + ((size_t)bb * LSEQ + l0) * NE);
        float4 a = c0[t], b = c1[t];
        a.x += b.x; a.y += b.y; a.z += b.z; a.w += b.w;
        dst[t] = a;   // 256 float4 = 16 rows * 64 floats, coalesced
    }
}

// ---------------------------------------------------------------------------
// Kernel 3: epilogue. Wo proj + residual + LN1 + FF + residual + LN2 for a
// 32-row tile; 512 threads, 16 threads per row.
// ---------------------------------------------------------------------------
#define E_OFF_W    0        // [3][4096] = 12288
#define E_OFF_VEC  12288    // 7*64 = 448
#define E_OFF_CTX  12736    // [32][68] = 2176
#define E_OFF_XROW 14912    // [32][68] = 2176
#define E_SMEM_FLOATS 17088 // 68,352 bytes

__global__ __launch_bounds__(512) void epi_kernel(
    const float* __restrict__ prev,
    const float* __restrict__ Wo, const float* __restrict__ bo,
    const float* __restrict__ ln1g, const float* __restrict__ ln1b,
    const float* __restrict__ W1, const float* __restrict__ b1,
    const float* __restrict__ W2, const float* __restrict__ b2,
    const float* __restrict__ ln2g, const float* __restrict__ ln2b,
    float* __restrict__ out)
{
    extern __shared__ float smf[];
    const int t  = threadIdx.x;
    const int bb = blockIdx.y;
    const int l0 = blockIdx.x * 32;

    // weights (transposed) + vectors + ctx tile
    {
        const float* Ws[3] = {Wo, W1, W2};
        #pragma unroll
        for (int m = 0; m < 3; m++) {
            const float4* w4 = reinterpret_cast<const float4*>(Ws[m]);
            #pragma unroll
            for (int ss = 0; ss < 2; ss++) {
                int f = t + 512 * ss;
                int c = f >> 4, e4 = f & 15;
                float4 v = w4[f];
                smf[E_OFF_W + m * 4096 + (e4 * 4 + 0) * 64 + c] = v.x;
                smf[E_OFF_W + m * 4096 + (e4 * 4 + 1) * 64 + c] = v.y;
                smf[E_OFF_W + m * 4096 + (e4 * 4 + 2) * 64 + c] = v.z;
                smf[E_OFF_W + m * 4096 + (e4 * 4 + 3) * 64 + c] = v.w;
            }
        }
        if (t < 64) {
            smf[E_OFF_VEC + 0 * 64 + t] = bo[t];
            smf[E_OFF_VEC + 1 * 64 + t] = b1[t];
            smf[E_OFF_VEC + 2 * 64 + t] = b2[t];
            smf[E_OFF_VEC + 3 * 64 + t] = ln1g[t];
            smf[E_OFF_VEC + 4 * 64 + t] = ln1b[t];
            smf[E_OFF_VEC + 5 * 64 + t] = ln2g[t];
            smf[E_OFF_VEC + 6 * 64 + t] = ln2b[t];
        }
        // ctx tile: 32 rows * 64 = 512 float4
        const float4* c4 = reinterpret_cast<const float4*>(
            g_ctx + ((size_t)bb * LSEQ + l0) * NE);
        int row = t >> 4, e4 = t & 15;
        *reinterpret_cast<float4*>(&smf[E_OFF_CTX + row * 68 + e4 * 4]) = c4[t];
    }
    __syncthreads();

    const int r  = t >> 4;
    const int cg = t & 15;
    const size_t grow = (size_t)bb * LSEQ + l0 + r;
    const float* ctx = smf + E_OFF_CTX;
    const float* wsm = smf + E_OFF_W;
    const float* vbo = smf + E_OFF_VEC;
    float* xrow = smf + E_OFF_XROW;

    float x0, x1, x2, x3;
    {
        float a0 = vbo[cg*4+0], a1 = vbo[cg*4+1], a2 = vbo[cg*4+2], a3 = vbo[cg*4+3];
        #pragma unroll 16
        for (int e = 0; e < 64; e++) {
            float xx = ctx[r * 68 + e];
            float4 w = *reinterpret_cast<const float4*>(&wsm[e * 64 + cg * 4]);
            a0 = fmaf(xx, w.x, a0); a1 = fmaf(xx, w.y, a1);
            a2 = fmaf(xx, w.z, a2); a3 = fmaf(xx, w.w, a3);
        }
        const float4 pv = *reinterpret_cast<const float4*>(&prev[grow * NE + cg * 4]);
        a0 += pv.x; a1 += pv.y; a2 += pv.z; a3 += pv.w;

        float psum = a0 + a1 + a2 + a3;
        #pragma unroll
        for (int o = 8; o >= 1; o >>= 1) psum += __shfl_xor_sync(0xffffffffu, psum, o);
        float mu = psum * (1.0f / 64.0f);
        float d0 = a0 - mu, d1 = a1 - mu, d2 = a2 - mu, d3 = a3 - mu;
        float psq = d0*d0 + d1*d1 + d2*d2 + d3*d3;
        #pragma unroll
        for (int o = 8; o >= 1; o >>= 1) psq += __shfl_xor_sync(0xffffffffu, psq, o);
        float rs = rsqrtf(psq * (1.0f / 64.0f) + LN_EPS);
        x0 = fmaf(d0 * rs, vbo[192+cg*4+0], vbo[256+cg*4+0]);
        x1 = fmaf(d1 * rs, vbo[192+cg*4+1], vbo[256+cg*4+1]);
        x2 = fmaf(d2 * rs, vbo[192+cg*4+2], vbo[256+cg*4+2]);
        x3 = fmaf(d3 * rs, vbo[192+cg*4+3], vbo[256+cg*4+3]);
        xrow[r*68 + cg*4+0] = x0; xrow[r*68 + cg*4+1] = x1;
        xrow[r*68 + cg*4+2] = x2; xrow[r*68 + cg*4+3] = x3;
    }
    __syncwarp();

    float h0, h1, h2, h3;
    {   // FF layer 1 + ReLU
        float a0 = vbo[64+cg*4+0], a1 = vbo[64+cg*4+1], a2 = vbo[64+cg*4+2], a3 = vbo[64+cg*4+3];
        #pragma unroll 16
        for (int e = 0; e < 64; e++) {
            float xx = xrow[r * 68 + e];
            float4 w = *reinterpret_cast<const float4*>(&wsm[4096 + e * 64 + cg * 4]);
            a0 = fmaf(xx, w.x, a0); a1 = fmaf(xx, w.y, a1);
            a2 = fmaf(xx, w.z, a2); a3 = fmaf(xx, w.w, a3);
        }
        h0 = fmaxf(a0, 0.f); h1 = fmaxf(a1, 0.f);
        h2 = fmaxf(a2, 0.f); h3 = fmaxf(a3, 0.f);
    }
    __syncwarp();
    xrow[r*68 + cg*4+0] = h0; xrow[r*68 + cg*4+1] = h1;
    xrow[r*68 + cg*4+2] = h2; xrow[r*68 + cg*4+3] = h3;
    __syncwarp();

    {   // FF layer 2 + residual + LN2 + output write
        float a0 = vbo[128+cg*4+0], a1 = vbo[128+cg*4+1], a2 = vbo[128+cg*4+2], a3 = vbo[128+cg*4+3];
        #pragma unroll 16
        for (int e = 0; e < 64; e++) {
            float hh = xrow[r * 68 + e];
            float4 w = *reinterpret_cast<const float4*>(&wsm[8192 + e * 64 + cg * 4]);
            a0 = fmaf(hh, w.x, a0); a1 = fmaf(hh, w.y, a1);
            a2 = fmaf(hh, w.z, a2); a3 = fmaf(hh, w.w, a3);
        }
        a0 += x0; a1 += x1; a2 += x2; a3 += x3;

        float psum = a0 + a1 + a2 + a3;
        #pragma unroll
        for (int o = 8; o >= 1; o >>= 1) psum += __shfl_xor_sync(0xffffffffu, psum, o);
        float mu = psum * (1.0f / 64.0f);
        float d0 = a0 - mu, d1 = a1 - mu, d2 = a2 - mu, d3 = a3 - mu;
        float psq = d0*d0 + d1*d1 + d2*d2 + d3*d3;
        #pragma unroll
        for (int o = 8; o >= 1; o >>= 1) psq += __shfl_xor_sync(0xffffffffu, psq, o);
        float rs = rsqrtf(psq * (1.0f / 64.0f) + LN_EPS);

        float4 o4;
        o4.x = fmaf(d0 * rs, vbo[320+cg*4+0], vbo[384+cg*4+0]);
        o4.y = fmaf(d1 * rs, vbo[320+cg*4+1], vbo[384+cg*4+1]);
        o4.z = fmaf(d2 * rs, vbo[320+cg*4+2], vbo[384+cg*4+2]);
        o4.w = fmaf(d3 * rs, vbo[320+cg*4+3], vbo[384+cg*4+3]);
        *reinterpret_cast<float4*>(&out[grow * NE + cg * 4]) = o4;
    }
}

// ---------------------------------------------------------------------------
extern "C" void kernel_launch(void* const* d_in, const int* in_sizes, int n_in,
                              void* d_out, int out_size)
{
    const float* q    = (const float*)d_in[0];
    const float* k    = (const float*)d_in[1];
    const float* prev = (const float*)d_in[2];
    const float* Wq   = (const float*)d_in[3];
    const float* bq   = (const float*)d_in[4];
    const float* Wk   = (const float*)d_in[5];
    const float* bk   = (const float*)d_in[6];
    const float* Wv   = (const float*)d_in[7];
    const float* bv   = (const float*)d_in[8];
    const float* Wo   = (const float*)d_in[9];
    const float* bo   = (const float*)d_in[10];
    const float* g1   = (const float*)d_in[11];
    const float* be1  = (const float*)d_in[12];
    const float* W1   = (const float*)d_in[13];
    const float* b1   = (const float*)d_in[14];
    const float* W2   = (const float*)d_in[15];
    const float* b2   = (const float*)d_in[16];
    const float* g2   = (const float*)d_in[17];
    const float* be2  = (const float*)d_in[18];

    float* out  = (float*)d_out;
    float* attn = out + (size_t)NB * LSEQ * NE;

    cudaFuncSetAttribute(proj_kernel, cudaFuncAttributeMaxDynamicSharedMemorySize,
                         (int)sizeof(Smem1));
    cudaFuncSetAttribute(attn_kernel, cudaFuncAttributeMaxDynamicSharedMemorySize,
                         A_SMEM_FLOATS * 4);
    cudaFuncSetAttribute(epi_kernel, cudaFuncAttributeMaxDynamicSharedMemorySize,
                         E_SMEM_FLOATS * 4);

    proj_kernel<<<(NB * LSEQ) / 64, 256, sizeof(Smem1)>>>(
        q, k, Wq, bq, Wk, bk, Wv, bv);
    attn_kernel<<<dim3(LSEQ / 16, NB), 256, A_SMEM_FLOATS * 4>>>(attn);
    epi_kernel<<<dim3(LSEQ / 32, NB), 512, E_SMEM_FLOATS * 4>>>(
        prev, Wo, bo, g1, be1, W1, b1, W2, b2, g2, be2, out);
}